// round 16
// baseline (speedup 1.0000x reference)
#include <cuda_runtime.h>
#include <cuda_fp16.h>
#include <math.h>
#include <stdint.h>

#define BATCH   128
#define T_STEPS 512
#define HID     1024
#define OUTF    128
#define GRID    128
#define NTHR    288          // 8 compute warps + 1 sync warp
#define NC      32
#define UPC     8
#define NSUPER  8            // super-chunks of 128 k-elems (2 x 64-chunks)
#define CS      34           // Csm row stride (floats) — even

// ---- persistent device state (zero-init; restored at kernel end for replay) ----
__device__ __half        g_h1[3][BATCH * HID];   // fp16 h, triple-buffered
__device__ float         g_hT[BATCH * HID];
__device__ unsigned int  g_prod[16];     // per unit-group producer counters
__device__ unsigned int  g_arrive;
__device__ volatile unsigned int g_sense;

// ---- smem layout (bytes) ----
#define OFF_BB 64                       // 32 floats: b_ih+b_hh
#define OFF_WI 192                      // 32 floats: w_ih
#define OFF_FL 384                      // 16 volatile ints: sync flags
#define OFF_W1 1024                     // W fp16: 16 chunk-tiles x 4KB = 64KB
#define OFF_A  (OFF_W1 + 65536)        // per-warp A rings: 8 x 3 x 4KB = 96KB
#define OFF_C  (OFF_A + 98304)         // C scratch: 34816B
#define SMEM_BYTES (OFF_C + 2 * BATCH * CS * 4)   // 199680

__device__ __forceinline__ uint32_t smem_u32(const void* p) {
    return (uint32_t)__cvta_generic_to_shared(p);
}
__device__ __forceinline__ void cp16(uint32_t s, const void* g) {
    asm volatile("cp.async.cg.shared.global [%0], [%1], 16;" :: "r"(s), "l"(g));
}
__device__ __forceinline__ void ldm4(uint32_t r[4], uint32_t addr) {
    asm volatile("ldmatrix.sync.aligned.m8n8.x4.shared.b16 {%0,%1,%2,%3}, [%4];"
                 : "=r"(r[0]), "=r"(r[1]), "=r"(r[2]), "=r"(r[3]) : "r"(addr));
}
__device__ __forceinline__ void mma16816h(float c[4], const uint32_t a[4],
                                          uint32_t b0, uint32_t b1) {
    asm volatile(
        "mma.sync.aligned.m16n8k16.row.col.f32.f16.f16.f32 "
        "{%0,%1,%2,%3},{%4,%5,%6,%7},{%8,%9},{%0,%1,%2,%3};"
        : "+f"(c[0]), "+f"(c[1]), "+f"(c[2]), "+f"(c[3])
        : "r"(a[0]), "r"(a[1]), "r"(a[2]), "r"(a[3]), "r"(b0), "r"(b1));
}
__device__ __forceinline__ uint32_t sw128(uint32_t off) {
    return off ^ ((off >> 3) & 0x70);
}
__device__ __forceinline__ float sigf(float x) {
    return 1.0f / (1.0f + __expf(-x));
}
__device__ __forceinline__ float tanhfast(float x) {
    return 2.0f / (1.0f + __expf(-2.0f * x)) - 1.0f;
}
__device__ __forceinline__ unsigned ldvol(const unsigned* p) {
    unsigned v;
    asm volatile("ld.volatile.global.u32 %0, [%1];" : "=r"(v) : "l"(p));
    return v;
}
__device__ __forceinline__ void wait_flag(volatile int* fp, int want) {
    while (*fp < want) __nanosleep(16);
    asm volatile("" ::: "memory");
}

__device__ __forceinline__ void grid_barrier(int tid, unsigned* local) {
    __syncthreads();
    if (tid == 0) {
        unsigned want = *local ^ 1u;
        *local = want;
        __threadfence();
        unsigned a = atomicAdd(&g_arrive, 1u);
        if (a == GRID - 1) {
            g_arrive = 0;
            __threadfence();
            g_sense = want;
        } else {
            while (g_sense != want) __nanosleep(32);
        }
        __threadfence();
    }
    __syncthreads();
}

__global__ void __launch_bounds__(NTHR, 1)
lstm_kernel(const float* __restrict__ y_hist,
            const float* __restrict__ W_ih,
            const float* __restrict__ W_hh,
            const float* __restrict__ b_ih,
            const float* __restrict__ b_hh,
            const float* __restrict__ fc_W,
            const float* __restrict__ fc_b,
            const float* __restrict__ h0,
            const float* __restrict__ c0,
            float* __restrict__ out)
{
    extern __shared__ char smem[];
    const uint32_t sb = smem_u32(smem);
    const int tid  = threadIdx.x;
    const int wid  = tid >> 5;
    const int lane = tid & 31;
    const int mw   = wid & 3;          // m-group (compute warps)
    const int kh   = (wid >> 2) & 1;   // k-half (compute warps)
    const int n0   = blockIdx.x * UPC;
    const int base = blockIdx.x >> 3;  // this CTA's unit group
    const int b    = tid & 127;
    const int half = (tid >> 7) & 1;
    const bool cw  = (wid < 8);        // compute warp?
    unsigned bar_sense = 0;

    volatile int* fl = (volatile int*)(smem + OFF_FL);
    if (tid < 16) fl[tid] = 0;

    // ---- h0 -> fp16, UNIT-owned ----
    for (int e = tid; e < BATCH * UPC; e += NTHR) {
        int br = e >> 3, u = e & 7;
        g_h1[0][br * HID + n0 + u] = __float2half_rn(h0[br * HID + n0 + u]);
    }

    // ---- One-time: W_hh slice -> fp16, SW128 chunk tiles in smem ----
    for (int e = tid; e < NC * HID; e += NTHR) {
        int lr = e >> 10, k = e & 1023;
        int u = lr >> 2, g = lr & 3;
        float w = W_hh[(g * HID + n0 + u) * HID + k];
        int kc  = k >> 6;
        uint32_t off = (uint32_t)(lr * 128 + (k & 63) * 2);
        *(__half*)(smem + OFF_W1 + kc * 4096 + sw128(off)) = __float2half_rn(w);
    }
    for (int e = tid; e < NC; e += NTHR) {
        int u = e >> 2, g = e & 3;
        int gr = g * HID + n0 + u;
        ((float*)(smem + OFF_BB))[e] = b_ih[gr] + b_hh[gr];
        ((float*)(smem + OFF_WI))[e] = W_ih[gr];
    }
    float c_reg[4];
#pragma unroll
    for (int u = 0; u < 4; u++)
        c_reg[u] = c0[b * HID + n0 + half * 4 + u];

    __syncthreads();
    if (tid == 0) {
        __threadfence();
        atomicAdd(&g_prod[base], 1u);
    }

    float* Csm = (float*)(smem + OFF_C);
    const float* bbp = (const float*)(smem + OFF_BB);
    const float* wip = (const float*)(smem + OFF_WI);

    const int arow = lane & 15;
    const int akb  = (lane >> 4) << 4;
    const int brow = (lane & 7) + ((lane & 16) >> 1);
    const int bkb  = (lane & 8) << 1;
    const uint32_t warp_ring = sb + OFF_A + wid * 12288;

    for (int s = 0; s < T_STEPS; s++) {
        float x = 0.f;
        const int rbuf = s % 3, wbuf = (s + 1) % 3;
        if (!cw) {
            // ======== SYNC WARP: poll producer counters, publish flags ========
            unsigned tgt = 8u * (unsigned)(s + 1);
            bool done = (lane >= 16);
            while (!__all_sync(0xffffffffu, done)) {
                if (!done && ldvol(&g_prod[lane]) >= tgt) {
                    __threadfence();
                    fl[lane] = s + 1;
                    done = true;
                }
                __nanosleep(16);
            }
            __syncthreads();                         // #1 (matches compute #1)
        } else {
            // ======== COMPUTE WARPS ========
            x = __ldg(&y_hist[b * T_STEPS + s]);
            const char* h1src = (const char*)g_h1[rbuf];
            const char* gb1 = h1src + (mw * 32) * 2048 + kh * 64;

            // prologue: super-chunks 0,1 (chunks 0..3)
#pragma unroll
            for (int pc = 0; pc < 2; pc++) {
                wait_flag(&fl[2 * pc], s + 1);
                wait_flag(&fl[2 * pc + 1], s + 1);
                uint32_t abase = warp_ring + pc * 4096;
#pragma unroll
                for (int i = 0; i < 8; i++) {
                    int f = i * 32 + lane;
                    int row = f >> 3, sub = f & 7;
                    int part = sub >> 2, seg = sub & 3;
                    uint32_t off = (uint32_t)(row * 128 + part * 64 + seg * 16);
                    cp16(abase + sw128(off),
                         gb1 + row * 2048 + (2 * pc + part) * 128 + seg * 16);
                }
                asm volatile("cp.async.commit_group;" ::: "memory");
            }

            float acc[2][4][4];
#pragma unroll
            for (int mt = 0; mt < 2; mt++)
#pragma unroll
                for (int nt = 0; nt < 4; nt++)
#pragma unroll
                    for (int q = 0; q < 4; q++)
                        acc[mt][nt][q] = 0.f;

            int stage = 0;
            for (int sc = 0; sc < NSUPER; sc++) {
                if (sc < NSUPER - 1)
                    asm volatile("cp.async.wait_group 1;" ::: "memory");
                else
                    asm volatile("cp.async.wait_group 0;" ::: "memory");
                __syncwarp();

                const uint32_t ab = warp_ring + stage * 4096;

                // ---- ALL 16 ldsm up front (max MLP, one latency exposure) ----
                uint32_t aF[4][2][4];   // [part*2+t][mt]
                uint32_t bF[4][2][4];   // [part*2+t][np]
#pragma unroll
                for (int pt = 0; pt < 4; pt++) {
                    const int part = pt >> 1, t = pt & 1;
#pragma unroll
                    for (int mt = 0; mt < 2; mt++) {
                        uint32_t ra = (uint32_t)((mt * 16 + arow) * 128
                                                 + part * 64 + t * 32);
                        ldm4(aF[pt][mt], ab + sw128(ra + akb));
                    }
                    const uint32_t w1b = sb + OFF_W1 + (2 * sc + part) * 4096;
                    const int kbb = kh * 64 + t * 32;
#pragma unroll
                    for (int np = 0; np < 2; np++) {
                        uint32_t off = (uint32_t)((np * 16 + brow) * 128
                                                  + kbb + bkb);
                        ldm4(bF[pt][np], w1b + sw128(off));
                    }
                }

                // prefetch super-chunk sc+2 (overlaps ldsm latency + MMAs)
                if (sc + 2 < NSUPER) {
                    wait_flag(&fl[2 * (sc + 2)], s + 1);
                    wait_flag(&fl[2 * (sc + 2) + 1], s + 1);
                    int ns = stage + 2; if (ns >= 3) ns -= 3;
                    uint32_t abase = warp_ring + ns * 4096;
#pragma unroll
                    for (int i = 0; i < 8; i++) {
                        int f = i * 32 + lane;
                        int row = f >> 3, sub = f & 7;
                        int part = sub >> 2, seg = sub & 3;
                        uint32_t off = (uint32_t)(row * 128 + part * 64 + seg * 16);
                        cp16(abase + sw128(off),
                             gb1 + row * 2048 + (2 * sc + 4 + part) * 128 + seg * 16);
                    }
                    asm volatile("cp.async.commit_group;" ::: "memory");
                }

                // ---- 32 HMMA as one stream ----
#pragma unroll
                for (int pt = 0; pt < 4; pt++)
#pragma unroll
                    for (int mt = 0; mt < 2; mt++)
#pragma unroll
                        for (int nt = 0; nt < 4; nt++) {
                            uint32_t b0 = bF[pt][nt >> 1][(nt & 1) * 2];
                            uint32_t b1 = bF[pt][nt >> 1][(nt & 1) * 2 + 1];
                            mma16816h(acc[mt][nt], aF[pt][mt], b0, b1);
                        }

                stage++; if (stage >= 3) stage = 0;
            }

            // ---- partial C fragments -> smem ----
            {
                float* Cp = Csm + kh * (BATCH * CS);
#pragma unroll
                for (int mt = 0; mt < 2; mt++) {
                    int r0 = mw * 32 + mt * 16 + (lane >> 2);
#pragma unroll
                    for (int nt = 0; nt < 4; nt++) {
                        int col = nt * 8 + (lane & 3) * 2;
                        *(float2*)(Cp + r0 * CS + col) =
                            make_float2(acc[mt][nt][0], acc[mt][nt][1]);
                        *(float2*)(Cp + (r0 + 8) * CS + col) =
                            make_float2(acc[mt][nt][2], acc[mt][nt][3]);
                    }
                }
            }
            __syncthreads();                         // #1: C published
        }

        if (cw) {
            unsigned short h1r[4];
            float hv4[4];
#pragma unroll
            for (int u = 0; u < 4; u++) {
                int ug = half * 4 + u;
                int c0i = b * CS + 4 * ug;
                int c1i = BATCH * CS + c0i;
                float gi = Csm[c0i + 0] + Csm[c1i + 0] + x * wip[4 * ug + 0] + bbp[4 * ug + 0];
                float gf = Csm[c0i + 1] + Csm[c1i + 1] + x * wip[4 * ug + 1] + bbp[4 * ug + 1];
                float gg = Csm[c0i + 2] + Csm[c1i + 2] + x * wip[4 * ug + 2] + bbp[4 * ug + 2];
                float go = Csm[c0i + 3] + Csm[c1i + 3] + x * wip[4 * ug + 3] + bbp[4 * ug + 3];
                float cn = sigf(gf) * c_reg[u] + sigf(gi) * tanhfast(gg);
                c_reg[u] = cn;
                float hv = sigf(go) * tanhfast(cn);
                hv4[u] = hv;
                h1r[u] = __half_as_ushort(__float2half_rn(hv));
            }
            // triple buffer: no WAR wait needed
            uint32_t p1[2];
#pragma unroll
            for (int q = 0; q < 2; q++)
                p1[q] = (uint32_t)h1r[2 * q] | ((uint32_t)h1r[2 * q + 1] << 16);
            *(uint2*)(&g_h1[wbuf][b * HID + n0 + half * 4]) = make_uint2(p1[0], p1[1]);
            if (s == T_STEPS - 1) {
#pragma unroll
                for (int u = 0; u < 4; u++)
                    g_hT[b * HID + n0 + half * 4 + u] = hv4[u];
            }
        }
        __syncthreads();                             // #2: all h stores done
        if (tid == 0) {
            __threadfence();
            atomicAdd(&g_prod[base], 1u);            // publish our units
        }
    }

    // ---- end: full barrier, reset counters for graph replay ----
    grid_barrier(tid, &bar_sense);
    if (blockIdx.x == 0 && tid < 16) g_prod[tid] = 0u;

    // ---- Final FC: CTA bb computes out[bb, 0..127] ----
    {
        int bb = blockIdx.x;
        float* hrow = (float*)(smem + OFF_A);
        if (tid < 256)
            ((float4*)hrow)[tid] = ((const float4*)(g_hT + bb * HID))[tid];
        __syncthreads();
        if (cw) {
            for (int o = wid; o < OUTF; o += 8) {
                const float* fw = fc_W + o * HID;
                float sum = 0.f;
                for (int kk = lane; kk < HID; kk += 32)
                    sum += hrow[kk] * __ldg(&fw[kk]);
#pragma unroll
                for (int dd = 16; dd; dd >>= 1)
                    sum += __shfl_xor_sync(0xffffffffu, sum, dd);
                if (lane == 0)
                    out[bb * OUTF + o] = sum + fc_b[o];
            }
        }
    }

    // final barrier: restores g_sense/g_arrive to 0 for replay
    grid_barrier(tid, &bar_sense);
}

extern "C" void kernel_launch(void* const* d_in, const int* in_sizes, int n_in,
                              void* d_out, int out_size)
{
    const float* y_hist = (const float*)d_in[0];
    const float* W_ih   = (const float*)d_in[1];
    const float* W_hh   = (const float*)d_in[2];
    const float* b_ih   = (const float*)d_in[3];
    const float* b_hh   = (const float*)d_in[4];
    const float* fc_W   = (const float*)d_in[5];
    const float* fc_b   = (const float*)d_in[6];
    const float* h0     = (const float*)d_in[7];
    const float* c0     = (const float*)d_in[8];
    float* out = (float*)d_out;

    cudaFuncSetAttribute(lstm_kernel,
                         cudaFuncAttributeMaxDynamicSharedMemorySize, SMEM_BYTES);

    lstm_kernel<<<GRID, NTHR, SMEM_BYTES>>>(y_hist, W_ih, W_hh, b_ih, b_hh,
                                            fc_W, fc_b, h0, c0, out);
}

// round 17
// speedup vs baseline: 1.1094x; 1.1094x over previous
#include <cuda_runtime.h>
#include <cuda_fp16.h>
#include <math.h>
#include <stdint.h>

#define BATCH   128
#define T_STEPS 512
#define HID     1024
#define OUTF    128
#define GRID    128
#define NTHR    288          // 8 compute warps + 1 sync warp
#define NC      32
#define UPC     8
#define NSUPER  8            // super-chunks of 128 k-elems (2 x 64-chunks)
#define CS      34           // Csm row stride (floats) — even

// ---- persistent device state (zero-init; restored at kernel end for replay) ----
__device__ __half        g_h1[3][BATCH * HID];   // fp16 h, triple-buffered
__device__ float         g_hT[BATCH * HID];
__device__ unsigned int  g_prod[16];     // per unit-group producer counters
__device__ unsigned int  g_arrive;
__device__ volatile unsigned int g_sense;

// ---- smem layout (bytes) ----
#define OFF_BB 64                       // 32 floats: b_ih+b_hh
#define OFF_WI 192                      // 32 floats: w_ih
#define OFF_FL 384                      // 16 volatile ints: sync flags
#define OFF_W1 1024                     // W fp16: 16 chunk-tiles x 4KB = 64KB
#define OFF_A  (OFF_W1 + 65536)        // per-warp A rings: 8 x 3 x 4KB = 96KB
#define OFF_C  (OFF_A + 98304)         // C scratch: 34816B
#define SMEM_BYTES (OFF_C + 2 * BATCH * CS * 4)   // 199680

__device__ __forceinline__ uint32_t smem_u32(const void* p) {
    return (uint32_t)__cvta_generic_to_shared(p);
}
__device__ __forceinline__ void cp16(uint32_t s, const void* g) {
    asm volatile("cp.async.cg.shared.global [%0], [%1], 16;" :: "r"(s), "l"(g));
}
__device__ __forceinline__ void ldm4(uint32_t r[4], uint32_t addr) {
    asm volatile("ldmatrix.sync.aligned.m8n8.x4.shared.b16 {%0,%1,%2,%3}, [%4];"
                 : "=r"(r[0]), "=r"(r[1]), "=r"(r[2]), "=r"(r[3]) : "r"(addr));
}
__device__ __forceinline__ void mma16816h(float c[4], const uint32_t a[4],
                                          uint32_t b0, uint32_t b1) {
    asm volatile(
        "mma.sync.aligned.m16n8k16.row.col.f32.f16.f16.f32 "
        "{%0,%1,%2,%3},{%4,%5,%6,%7},{%8,%9},{%0,%1,%2,%3};"
        : "+f"(c[0]), "+f"(c[1]), "+f"(c[2]), "+f"(c[3])
        : "r"(a[0]), "r"(a[1]), "r"(a[2]), "r"(a[3]), "r"(b0), "r"(b1));
}
__device__ __forceinline__ uint32_t sw128(uint32_t off) {
    return off ^ ((off >> 3) & 0x70);
}
__device__ __forceinline__ float sigf(float x) {
    return 1.0f / (1.0f + __expf(-x));
}
__device__ __forceinline__ float tanhfast(float x) {
    return 2.0f / (1.0f + __expf(-2.0f * x)) - 1.0f;
}
__device__ __forceinline__ unsigned ldvol(const unsigned* p) {
    unsigned v;
    asm volatile("ld.volatile.global.u32 %0, [%1];" : "=r"(v) : "l"(p));
    return v;
}
__device__ __forceinline__ void wait_flag(volatile int* fp, int want) {
    while (*fp < want) __nanosleep(32);
    asm volatile("" ::: "memory");
}

__device__ __forceinline__ void grid_barrier(int tid, unsigned* local) {
    __syncthreads();
    if (tid == 0) {
        unsigned want = *local ^ 1u;
        *local = want;
        __threadfence();
        unsigned a = atomicAdd(&g_arrive, 1u);
        if (a == GRID - 1) {
            g_arrive = 0;
            __threadfence();
            g_sense = want;
        } else {
            while (g_sense != want) __nanosleep(32);
        }
        __threadfence();
    }
    __syncthreads();
}

__global__ void __launch_bounds__(NTHR, 1)
lstm_kernel(const float* __restrict__ y_hist,
            const float* __restrict__ W_ih,
            const float* __restrict__ W_hh,
            const float* __restrict__ b_ih,
            const float* __restrict__ b_hh,
            const float* __restrict__ fc_W,
            const float* __restrict__ fc_b,
            const float* __restrict__ h0,
            const float* __restrict__ c0,
            float* __restrict__ out)
{
    extern __shared__ char smem[];
    const uint32_t sb = smem_u32(smem);
    const int tid  = threadIdx.x;
    const int wid  = tid >> 5;
    const int lane = tid & 31;
    const int mw   = wid & 3;          // m-group (compute warps)
    const int kh   = (wid >> 2) & 1;   // k-half (compute warps)
    const int n0   = blockIdx.x * UPC;
    const int base = blockIdx.x >> 3;  // this CTA's unit group
    const int b    = tid & 127;
    const int half = (tid >> 7) & 1;
    const bool cw  = (wid < 8);        // compute warp?
    unsigned bar_sense = 0;

    volatile int* fl = (volatile int*)(smem + OFF_FL);
    if (tid < 16) fl[tid] = 0;

    // ---- h0 -> fp16, UNIT-owned ----
    for (int e = tid; e < BATCH * UPC; e += NTHR) {
        int br = e >> 3, u = e & 7;
        g_h1[0][br * HID + n0 + u] = __float2half_rn(h0[br * HID + n0 + u]);
    }

    // ---- One-time: W_hh slice -> fp16, SW128 chunk tiles in smem ----
    for (int e = tid; e < NC * HID; e += NTHR) {
        int lr = e >> 10, k = e & 1023;
        int u = lr >> 2, g = lr & 3;
        float w = W_hh[(g * HID + n0 + u) * HID + k];
        int kc  = k >> 6;
        uint32_t off = (uint32_t)(lr * 128 + (k & 63) * 2);
        *(__half*)(smem + OFF_W1 + kc * 4096 + sw128(off)) = __float2half_rn(w);
    }
    for (int e = tid; e < NC; e += NTHR) {
        int u = e >> 2, g = e & 3;
        int gr = g * HID + n0 + u;
        ((float*)(smem + OFF_BB))[e] = b_ih[gr] + b_hh[gr];
        ((float*)(smem + OFF_WI))[e] = W_ih[gr];
    }
    float c_reg[4];
#pragma unroll
    for (int u = 0; u < 4; u++)
        c_reg[u] = c0[b * HID + n0 + half * 4 + u];

    __syncthreads();
    if (tid == 0) {
        __threadfence();
        atomicAdd(&g_prod[base], 1u);
    }

    float* Csm = (float*)(smem + OFF_C);
    const float* bbp = (const float*)(smem + OFF_BB);
    const float* wip = (const float*)(smem + OFF_WI);

    const int arow = lane & 15;
    const int akb  = (lane >> 4) << 4;
    const int brow = (lane & 7) + ((lane & 16) >> 1);
    const int bkb  = (lane & 8) << 1;
    const uint32_t warp_ring = sb + OFF_A + wid * 12288;

    for (int s = 0; s < T_STEPS; s++) {
        float x = 0.f;
        const int rbuf = s % 3, wbuf = (s + 1) % 3;
        if (!cw) {
            // ======== SYNC WARP: poll producer counters, publish flags ========
            unsigned tgt = 8u * (unsigned)(s + 1);
            bool done = (lane >= 16);
            while (!__all_sync(0xffffffffu, done)) {
                if (!done && ldvol(&g_prod[lane]) >= tgt) {
                    __threadfence();
                    fl[lane] = s + 1;
                    done = true;
                }
                __nanosleep(64);
            }
            __syncthreads();                         // #1 (matches compute #1)
        } else {
            // ======== COMPUTE WARPS ========
            x = __ldg(&y_hist[b * T_STEPS + s]);
            const char* h1src = (const char*)g_h1[rbuf];
            const char* gb1 = h1src + (mw * 32) * 2048 + kh * 64;

            // prologue: super-chunks 0,1 (chunks 0..3)
#pragma unroll
            for (int pc = 0; pc < 2; pc++) {
                wait_flag(&fl[2 * pc], s + 1);
                wait_flag(&fl[2 * pc + 1], s + 1);
                uint32_t abase = warp_ring + pc * 4096;
#pragma unroll
                for (int i = 0; i < 8; i++) {
                    int f = i * 32 + lane;
                    int row = f >> 3, sub = f & 7;
                    int part = sub >> 2, seg = sub & 3;
                    uint32_t off = (uint32_t)(row * 128 + part * 64 + seg * 16);
                    cp16(abase + sw128(off),
                         gb1 + row * 2048 + (2 * pc + part) * 128 + seg * 16);
                }
                asm volatile("cp.async.commit_group;" ::: "memory");
            }

            float acc[2][4][4];
#pragma unroll
            for (int mt = 0; mt < 2; mt++)
#pragma unroll
                for (int nt = 0; nt < 4; nt++)
#pragma unroll
                    for (int q = 0; q < 4; q++)
                        acc[mt][nt][q] = 0.f;

            int stage = 0;
            for (int sc = 0; sc < NSUPER; sc++) {
                if (sc < NSUPER - 1)
                    asm volatile("cp.async.wait_group 1;" ::: "memory");
                else
                    asm volatile("cp.async.wait_group 0;" ::: "memory");
                __syncwarp();

                const uint32_t ab = warp_ring + stage * 4096;

                // double-buffered quarter fragments (distance-1 pipeline)
                uint32_t aQ[2][2][4], bQ[2][2][4];

                // load quarter 0 (part 0, t 0)
                {
#pragma unroll
                    for (int mt = 0; mt < 2; mt++) {
                        uint32_t ra = (uint32_t)((mt * 16 + arow) * 128);
                        ldm4(aQ[0][mt], ab + sw128(ra + akb));
                    }
                    const uint32_t w1b = sb + OFF_W1 + (2 * sc) * 4096;
                    const int kbb = kh * 64;
#pragma unroll
                    for (int np = 0; np < 2; np++) {
                        uint32_t off = (uint32_t)((np * 16 + brow) * 128
                                                  + kbb + bkb);
                        ldm4(bQ[0][np], w1b + sw128(off));
                    }
                }

                // prefetch super-chunk sc+2 (overlaps quarter-0 ldsm latency)
                if (sc + 2 < NSUPER) {
                    wait_flag(&fl[2 * (sc + 2)], s + 1);
                    wait_flag(&fl[2 * (sc + 2) + 1], s + 1);
                    int ns = stage + 2; if (ns >= 3) ns -= 3;
                    uint32_t abase = warp_ring + ns * 4096;
#pragma unroll
                    for (int i = 0; i < 8; i++) {
                        int f = i * 32 + lane;
                        int row = f >> 3, sub = f & 7;
                        int part = sub >> 2, seg = sub & 3;
                        uint32_t off = (uint32_t)(row * 128 + part * 64 + seg * 16);
                        cp16(abase + sw128(off),
                             gb1 + row * 2048 + (2 * sc + 4 + part) * 128 + seg * 16);
                    }
                    asm volatile("cp.async.commit_group;" ::: "memory");
                }

                // pipelined quarters: load pt+1, then MMA pt
#pragma unroll
                for (int pt = 0; pt < 4; pt++) {
                    if (pt < 3) {
                        const int npt = pt + 1;
                        const int part = npt >> 1, t = npt & 1;
#pragma unroll
                        for (int mt = 0; mt < 2; mt++) {
                            uint32_t ra = (uint32_t)((mt * 16 + arow) * 128
                                                     + part * 64 + t * 32);
                            ldm4(aQ[npt & 1][mt], ab + sw128(ra + akb));
                        }
                        const uint32_t w1b = sb + OFF_W1
                                           + (2 * sc + part) * 4096;
                        const int kbb = kh * 64 + t * 32;
#pragma unroll
                        for (int np = 0; np < 2; np++) {
                            uint32_t off = (uint32_t)((np * 16 + brow) * 128
                                                      + kbb + bkb);
                            ldm4(bQ[npt & 1][np], w1b + sw128(off));
                        }
                    }
#pragma unroll
                    for (int mt = 0; mt < 2; mt++)
#pragma unroll
                        for (int nt = 0; nt < 4; nt++) {
                            uint32_t b0 = bQ[pt & 1][nt >> 1][(nt & 1) * 2];
                            uint32_t b1 = bQ[pt & 1][nt >> 1][(nt & 1) * 2 + 1];
                            mma16816h(acc[mt][nt], aQ[pt & 1][mt], b0, b1);
                        }
                }

                stage++; if (stage >= 3) stage = 0;
            }

            // ---- partial C fragments -> smem ----
            {
                float* Cp = Csm + kh * (BATCH * CS);
#pragma unroll
                for (int mt = 0; mt < 2; mt++) {
                    int r0 = mw * 32 + mt * 16 + (lane >> 2);
#pragma unroll
                    for (int nt = 0; nt < 4; nt++) {
                        int col = nt * 8 + (lane & 3) * 2;
                        *(float2*)(Cp + r0 * CS + col) =
                            make_float2(acc[mt][nt][0], acc[mt][nt][1]);
                        *(float2*)(Cp + (r0 + 8) * CS + col) =
                            make_float2(acc[mt][nt][2], acc[mt][nt][3]);
                    }
                }
            }
            __syncthreads();                         // #1: C published
        }

        if (cw) {
            unsigned short h1r[4];
            float hv4[4];
#pragma unroll
            for (int u = 0; u < 4; u++) {
                int ug = half * 4 + u;
                int c0i = b * CS + 4 * ug;
                int c1i = BATCH * CS + c0i;
                float gi = Csm[c0i + 0] + Csm[c1i + 0] + x * wip[4 * ug + 0] + bbp[4 * ug + 0];
                float gf = Csm[c0i + 1] + Csm[c1i + 1] + x * wip[4 * ug + 1] + bbp[4 * ug + 1];
                float gg = Csm[c0i + 2] + Csm[c1i + 2] + x * wip[4 * ug + 2] + bbp[4 * ug + 2];
                float go = Csm[c0i + 3] + Csm[c1i + 3] + x * wip[4 * ug + 3] + bbp[4 * ug + 3];
                float cn = sigf(gf) * c_reg[u] + sigf(gi) * tanhfast(gg);
                c_reg[u] = cn;
                float hv = sigf(go) * tanhfast(cn);
                hv4[u] = hv;
                h1r[u] = __half_as_ushort(__float2half_rn(hv));
            }
            // triple buffer: no WAR wait needed
            uint32_t p1[2];
#pragma unroll
            for (int q = 0; q < 2; q++)
                p1[q] = (uint32_t)h1r[2 * q] | ((uint32_t)h1r[2 * q + 1] << 16);
            *(uint2*)(&g_h1[wbuf][b * HID + n0 + half * 4]) = make_uint2(p1[0], p1[1]);
            if (s == T_STEPS - 1) {
#pragma unroll
                for (int u = 0; u < 4; u++)
                    g_hT[b * HID + n0 + half * 4 + u] = hv4[u];
            }
        }
        __syncthreads();                             // #2: all h stores done
        if (tid == 0) {
            __threadfence();
            atomicAdd(&g_prod[base], 1u);            // publish our units
        }
    }

    // ---- end: full barrier, reset counters for graph replay ----
    grid_barrier(tid, &bar_sense);
    if (blockIdx.x == 0 && tid < 16) g_prod[tid] = 0u;

    // ---- Final FC: CTA bb computes out[bb, 0..127] ----
    {
        int bb = blockIdx.x;
        float* hrow = (float*)(smem + OFF_A);
        if (tid < 256)
            ((float4*)hrow)[tid] = ((const float4*)(g_hT + bb * HID))[tid];
        __syncthreads();
        if (cw) {
            for (int o = wid; o < OUTF; o += 8) {
                const float* fw = fc_W + o * HID;
                float sum = 0.f;
                for (int kk = lane; kk < HID; kk += 32)
                    sum += hrow[kk] * __ldg(&fw[kk]);
#pragma unroll
                for (int dd = 16; dd; dd >>= 1)
                    sum += __shfl_xor_sync(0xffffffffu, sum, dd);
                if (lane == 0)
                    out[bb * OUTF + o] = sum + fc_b[o];
            }
        }
    }

    // final barrier: restores g_sense/g_arrive to 0 for replay
    grid_barrier(tid, &bar_sense);
}

extern "C" void kernel_launch(void* const* d_in, const int* in_sizes, int n_in,
                              void* d_out, int out_size)
{
    const float* y_hist = (const float*)d_in[0];
    const float* W_ih   = (const float*)d_in[1];
    const float* W_hh   = (const float*)d_in[2];
    const float* b_ih   = (const float*)d_in[3];
    const float* b_hh   = (const float*)d_in[4];
    const float* fc_W   = (const float*)d_in[5];
    const float* fc_b   = (const float*)d_in[6];
    const float* h0     = (const float*)d_in[7];
    const float* c0     = (const float*)d_in[8];
    float* out = (float*)d_out;

    cudaFuncSetAttribute(lstm_kernel,
                         cudaFuncAttributeMaxDynamicSharedMemorySize, SMEM_BYTES);

    lstm_kernel<<<GRID, NTHR, SMEM_BYTES>>>(y_hist, W_ih, W_hh, b_ih, b_hh,
                                            fc_W, fc_b, h0, c0, out);
}